// round 17
// baseline (speedup 1.0000x reference)
#include <cuda_runtime.h>
#include <cuda_fp16.h>
#include <stdint.h>
#include <math.h>

#define BB 8
#define HH 64
#define WW 64
#define CC 256
#define NPIX (BB*HH*WW)          // 32768

// ---------------- device scratch ----------------
__device__ __half g_yh[NPIX*CC];   // blurred x, fp16
__device__ __half g_Wh[CC*CC];     // fused weight W = proj_w @ v_w, fp16

// ---------------- helpers ----------------
__device__ __forceinline__ uint32_t smem_u32(const void* p) {
    uint32_t a;
    asm("{ .reg .u64 t; cvta.to.shared.u64 t, %1; cvt.u32.u64 %0, t; }" : "=r"(a) : "l"(p));
    return a;
}
__device__ __forceinline__ uint64_t gmem_u64(const void* p) {
    uint64_t a;
    asm("cvta.to.global.u64 %0, %1;" : "=l"(a) : "l"(p));
    return a;
}
#define CP_ASYNC16(sa, ga) \
    asm volatile("cp.async.cg.shared.global [%0], [%1], 16;" :: "r"(sa), "l"(ga))
#define CP_COMMIT() asm volatile("cp.async.commit_group;")
#define CP_WAIT(n)  asm volatile("cp.async.wait_group %0;" :: "n"(n))

#define LDMATRIX_X4(r0, r1, r2, r3, addr) \
    asm volatile("ldmatrix.sync.aligned.m8n8.x4.shared.b16 {%0,%1,%2,%3}, [%4];" \
        : "=r"(r0), "=r"(r1), "=r"(r2), "=r"(r3) : "r"(addr))

#define MMA_16816_F16(c, a, b0, b1) \
    asm volatile("mma.sync.aligned.m16n8k16.row.col.f32.f16.f16.f32 " \
        "{%0,%1,%2,%3}, {%4,%5,%6,%7}, {%8,%9}, {%0,%1,%2,%3};" \
        : "+f"((c)[0]), "+f"((c)[1]), "+f"((c)[2]), "+f"((c)[3]) \
        : "r"((a)[0]), "r"((a)[1]), "r"((a)[2]), "r"((a)[3]), "r"(b0), "r"(b1))

static __device__ __forceinline__ float4 f4add(float4 a, float4 b) {
    return make_float4(a.x+b.x, a.y+b.y, a.z+b.z, a.w+b.w);
}

// ============================================================================
// K1: prep.
//  Blocks [0,1024): blur v4 (SINGLE-SHOT) -> g_yh.
//   Block = (b, 16-row seg, 2-c4 group). Entire 18-row input tile loaded in
//   ONE cp.async burst (9 chunks/thread) -> one wait -> ONE syncthreads ->
//   all 16 output rows computed barrier-free. smem [row][c4i][w]: both the
//   cp.async stores and the compute LDS are conflict-free.
//  Blocks [1024,1088): W = proj_w @ v_w (smem-staged panel, validated).
// ============================================================================
#define BLUR_SMEM (18 * 2 * 64 * 16)     // 36864B

__global__ __launch_bounds__(256) void prep_kernel(const float* __restrict__ x,
                                                   const float* __restrict__ vw,
                                                   const float* __restrict__ pw) {
    __shared__ __align__(16) char sbuf[BLUR_SMEM];   // Wfuse needs 32896 <= this
    int bid = blockIdx.x;
    int tid = threadIdx.x;
    if (bid < 1024) {
        float4* S = (float4*)sbuf;           // idx = (r*2 + c4i)*64 + w
        uint32_t S_u = smem_u32(sbuf);
        int b   = bid >> 7;                  // 8
        int seg = (bid >> 5) & 3;            // 4 segs of 16 rows
        int cg  = bid & 31;                  // 32 groups of 2 c4
        int h0  = seg * 16;
        int c4a = cg * 2;
        const float e  = 2.718281828459045f;
        const float wo = 1.0f / (e + 8.0f);
        const float wd = e * wo - wo;
        const float4 Z = make_float4(0.f, 0.f, 0.f, 0.f);

        // ---- load phase: 18 rows x 2 c4 x 64 w = 2304 chunks, 9/thread ----
        #pragma unroll
        for (int k = 0; k < 9; k++) {
            int q  = k * 256 + tid;
            int r  = q >> 7;                 // 0..17
            int ci = (q >> 6) & 1;
            int lw = q & 63;
            int gr = h0 - 1 + r;
            int sidx = (r * 2 + ci) * 64 + lw;
            if (gr >= 0 && gr < HH) {
                CP_ASYNC16(S_u + sidx * 16,
                           gmem_u64(x + ((((size_t)b * HH + gr) * WW + lw) * 64 + c4a + ci) * 4));
            } else {
                S[sidx] = Z;
            }
        }
        CP_COMMIT();
        CP_WAIT(0);
        __syncthreads();                      // the ONLY barrier

        // ---- compute phase: thread = (w, row-group of 4) ----
        int w  = tid & 63;
        int rg = tid >> 6;                    // 0..3 -> output rows rg*4..rg*4+3
        #pragma unroll
        for (int t = 0; t < 2; t++) {
            int ci = t;
            int c4 = c4a + t;
            auto load_hs = [&](int sr, float4& hs, float4& xlv) {
                const float4* row = S + (sr * 2 + ci) * 64;
                float4 xl = (w > 0)  ? row[w - 1] : Z;
                float4 xc =            row[w];
                float4 xr = (w < 63) ? row[w + 1] : Z;
                hs = f4add(f4add(xl, xc), xr);
                xlv = xl;
            };
            float4 hsA, hsB, xlA, xlB;
            load_hs(rg * 4,     hsA, xlA);
            load_hs(rg * 4 + 1, hsB, xlB);
            #pragma unroll
            for (int jj = 0; jj < 4; jj++) {
                float4 hsC, xlC;
                load_hs(rg * 4 + 2 + jj, hsC, xlC);
                float4 o;
                o.x = wo * (hsA.x + hsB.x + hsC.x) + wd * xlA.x;
                o.y = wo * (hsA.y + hsB.y + hsC.y) + wd * xlA.y;
                o.z = wo * (hsA.z + hsB.z + hsC.z) + wd * xlA.z;
                o.w = wo * (hsA.w + hsB.w + hsC.w) + wd * xlA.w;
                union { __half h4[4]; uint2 u; } Hi;
                Hi.h4[0] = __float2half_rn(o.x);
                Hi.h4[1] = __float2half_rn(o.y);
                Hi.h4[2] = __float2half_rn(o.z);
                Hi.h4[3] = __float2half_rn(o.w);
                int h = h0 + rg * 4 + jj;
                size_t oq = (((size_t)b * HH + h) * WW + w) * 64 + c4;
                ((uint2*)g_yh)[oq] = Hi.u;
                hsA = hsB; xlA = xlB;
                hsB = hsC; xlB = xlC;
            }
        }
    } else {
        // ---- W-fuse: smem-staged vw panel (validated ~3us) ----
        float4* Bs4 = (float4*)sbuf;          // [chunk 0..7][d 0..255], stride 257
        int q  = bid - 1024;
        int e0 = (q >> 3) * 32;
        int c0 = (q & 7) * 32;
        const float4* vw4 = (const float4*)vw;
        #pragma unroll
        for (int j = 0; j < 8; j++)
            Bs4[j * 257 + tid] = vw4[tid * 64 + (c0 >> 2) + j];
        __syncthreads();

        int er = e0 + (tid >> 3);
        int c8 = tid & 7;
        const float* prow = pw + er * 256;
        const float4* Bcol = Bs4 + c8 * 257;
        float a0 = 0.f, a1 = 0.f, a2 = 0.f, a3 = 0.f;
        #pragma unroll 8
        for (int d = 0; d < 256; d++) {
            float a = prow[d];
            float4 bv = Bcol[d];
            a0 += a * bv.x; a1 += a * bv.y; a2 += a * bv.z; a3 += a * bv.w;
        }
        union { __half h4[4]; uint2 u; } Hi;
        Hi.h4[0] = __float2half_rn(a0);
        Hi.h4[1] = __float2half_rn(a1);
        Hi.h4[2] = __float2half_rn(a2);
        Hi.h4[3] = __float2half_rn(a3);
        *(uint2*)(g_Wh + er * 256 + c0 + c8 * 4) = Hi.u;
    }
}

// ============================================================================
// K2: out = y @ W^T + bias; single fp16 term, fp32 accum.  (FROZEN, 25.5us)
//   Persistent 2-tile CTA, grid (2,128); B resident; A 3-slot ring.
// ============================================================================
#define B_STRIDE 528
#define B_BYTES  (128 * B_STRIDE)        // 67584
#define A_SLOT   10240                   // 128 * 80
#define SMEM_TOTAL (B_BYTES + 3 * A_SLOT)  // 98304 (96KB) -> 2 CTAs/SM

__global__ __launch_bounds__(256, 2) void gemm_mma_kernel(const float* __restrict__ bias,
                                                          float* __restrict__ out) {
    extern __shared__ __align__(16) char smem[];
    uint32_t sbB = smem_u32(smem);
    uint32_t sbA = sbB + B_BYTES;
    int tid  = threadIdx.x;
    int wid  = tid >> 5;
    int lane = tid & 31;
    int bn = blockIdx.x * 128;
    int by = blockIdx.y;               // 0..127
    int wn = wid & 1;
    int wm = wid >> 1;

    float acc[2][8][4] = {};

    #pragma unroll
    for (int i = 0; i < 16; i++) {
        int q = i * 256 + tid;
        int row = q >> 5, c16 = q & 31;
        CP_ASYNC16(sbB + row * B_STRIDE + c16 * 16,
                   gmem_u64(g_Wh + (size_t)(bn + row) * 256 + c16 * 8));
    }

    auto issue_A = [&](int n) {
        int kc = n & 7;
        int slot = n % 3;
        size_t bm = (size_t)by * 128 + (size_t)(n >> 3) * 16384;
        #pragma unroll
        for (int j = 0; j < 2; j++) {
            int q = tid * 2 + j;
            int row = q >> 2, seg = q & 3;
            CP_ASYNC16(sbA + slot * A_SLOT + row * 80 + seg * 16,
                       gmem_u64(g_yh + (bm + row) * 256 + kc * 32 + seg * 8));
        }
    };

    issue_A(0); CP_COMMIT();
    issue_A(1); CP_COMMIT();

    #pragma unroll
    for (int t = 0; t < 2; t++) {
        #pragma unroll
        for (int kc = 0; kc < 8; kc++) {
            int r = t * 8 + kc;
            if (r < 15) { CP_WAIT(1); } else { CP_WAIT(0); }
            __syncthreads();
            if (r + 2 < 16) issue_A(r + 2);
            CP_COMMIT();

            uint32_t aB = sbA + (r % 3) * A_SLOT;

            #pragma unroll
            for (int ks = 0; ks < 2; ks++) {
                uint32_t af[2][4], bf[4][4];
                #pragma unroll
                for (int mi = 0; mi < 2; mi++) {
                    int row = wm * 32 + mi * 16 + (lane & 15);
                    uint32_t ao = row * 80 + ks * 32 + (lane >> 4) * 16;
                    LDMATRIX_X4(af[mi][0], af[mi][1], af[mi][2], af[mi][3], aB + ao);
                }
                #pragma unroll
                for (int ng = 0; ng < 4; ng++) {
                    int row = wn * 64 + ng * 16 + (lane & 15);
                    uint32_t bo = row * B_STRIDE + kc * 64 + ks * 32 + (lane >> 4) * 16;
                    LDMATRIX_X4(bf[ng][0], bf[ng][1], bf[ng][2], bf[ng][3], sbB + bo);
                }
                #pragma unroll
                for (int mi = 0; mi < 2; mi++)
                    #pragma unroll
                    for (int ng = 0; ng < 4; ng++) {
                        MMA_16816_F16(acc[mi][ng * 2 + 0], af[mi], bf[ng][0], bf[ng][2]);
                        MMA_16816_F16(acc[mi][ng * 2 + 1], af[mi], bf[ng][1], bf[ng][3]);
                    }
            }
        }

        size_t bmt = (size_t)by * 128 + (size_t)t * 16384;
        #pragma unroll
        for (int mi = 0; mi < 2; mi++) {
            size_t r0 = bmt + wm * 32 + mi * 16 + (lane >> 2);
            #pragma unroll
            for (int ni = 0; ni < 8; ni++) {
                int c = bn + wn * 64 + ni * 8 + (lane & 3) * 2;
                float b0 = __ldg(bias + c);
                float b1 = __ldg(bias + c + 1);
                float2 o0 = make_float2(acc[mi][ni][0] + b0, acc[mi][ni][1] + b1);
                float2 o1 = make_float2(acc[mi][ni][2] + b0, acc[mi][ni][3] + b1);
                *(float2*)(out + r0 * 256 + c) = o0;
                *(float2*)(out + (r0 + 8) * 256 + c) = o1;
            }
        }
        if (t == 0) {
            #pragma unroll
            for (int mi = 0; mi < 2; mi++)
                #pragma unroll
                for (int ni = 0; ni < 8; ni++)
                    #pragma unroll
                    for (int v = 0; v < 4; v++) acc[mi][ni][v] = 0.f;
        }
    }
}

// ============================================================================
extern "C" void kernel_launch(void* const* d_in, const int* in_sizes, int n_in,
                              void* d_out, int out_size) {
    const float* x  = (const float*)d_in[0];
    const float* vw = (const float*)d_in[1];
    const float* pw = (const float*)d_in[2];
    const float* pb = (const float*)d_in[3];
    float* out = (float*)d_out;

    cudaFuncSetAttribute(gemm_mma_kernel, cudaFuncAttributeMaxDynamicSharedMemorySize, SMEM_TOTAL);

    prep_kernel<<<1024 + 64, 256>>>(x, vw, pw);
    gemm_mma_kernel<<<dim3(2, 128), 256, SMEM_TOTAL>>>(pb, out);
}